// round 16
// baseline (speedup 1.0000x reference)
#include <cuda_runtime.h>
#include <cuda_fp16.h>

// Problem constants (fixed by the dataset)
#define N_TOTAL   10000
#define NUM_ATOMS 100
#define N_EDGES   1000000
#define NCL 38
#define NFL 12

#define EDGE_BLOCKS  888          // 6 per SM
#define EDGE_THREADS 256
#define EPT 2
#define EDGE_CHUNK   1128         // 888 * 1128 = 1,001,664 >= 1e6; even

// Scratch (alloc-free rule: __device__ globals)
__device__ float4 g_NA[N_TOTAL];   // {x, a(i-role), b(j-role), half2(sin,cos)}

__device__ __forceinline__ float safe_inv_f(float v) {
    float w = (fabsf(v) < 0.01f) ? ((v >= 0.0f) ? 0.01f : -0.01f) : v;
    return __fdividef(1.0f, w);
}

// ---------------- node pass: F(x) -> out, plus packed per-node table ----------------
__global__ void node_kernel(const float* __restrict__ x,
                            const float* __restrict__ c_mask,
                            const float* __restrict__ f_mask,
                            const float* __restrict__ wc2,
                            const float* __restrict__ wf2,
                            float* __restrict__ out) {
    __shared__ float swc[NCL];
    __shared__ float swf[NFL];
    int t = threadIdx.x;
    if (t < NCL) swc[t] = c_mask[t] * (wc2[t] - wc2[t + NCL]);
    if (t < NFL) swf[t] = f_mask[t] * (wf2[t] - wf2[t + NFL]);
    __syncthreads();

    int n = blockIdx.x * blockDim.x + t;
    if (n >= N_TOTAL) return;
    float xv = x[n];
    float s, c;
    __sincosf(xv, &s, &c);
    float E = __expf(-xv);
    float R = __expf(xv);
    float inv  = safe_inv_f(xv);
    float inv2 = inv * inv;
    float th = (R - E) * __fdividef(1.0f, R + E);     // tanh(x)
    float sg = __fdividef(1.0f, 1.0f + E);            // sigmoid(x)
    float rl = fmaxf(xv, 0.0f);
    float x2 = xv * xv;

    float F = swf[0]
            + swf[1]*s + swf[2]*c + swf[3]*xv*s
            + swf[4]*xv + swf[5]*x2
            + swf[6]*inv + swf[7]*inv2 + swf[8]*inv2*inv
            + swf[9]*th + swf[10]*sg + swf[11]*rl;
    out[n] = F;   // F_COEF = 1; edge kernel accumulates on top

    // node-as-x_i contribution (feature idx 0,3,6,10,18,19,26,27,28)
    float a = swc[0]*xv + swc[3]*x2 + swc[6]*inv + swc[10]*inv2
            + swc[18]*s + swc[19]*c + swc[26]*th + swc[27]*sg + swc[28]*rl;
    // node-as-x_j contribution (feature idx 1,4,7,11,20,21,29,30,31)
    float b = swc[1]*xv + swc[4]*x2 + swc[7]*inv + swc[11]*inv2
            + swc[20]*s + swc[21]*c + swc[29]*th + swc[30]*sg + swc[31]*rl;

    __half2 sc = __floats2half2_rn(s, c);
    g_NA[n] = make_float4(xv, a, b, __uint_as_float(*reinterpret_cast<unsigned*>(&sc)));
}

// ---------------- edge pass: all-L1 gathers + atomics; PDL-gated ----------------
__global__ void __launch_bounds__(EDGE_THREADS, 6)
edge_kernel(const void* __restrict__ eidx_raw,
            const float* __restrict__ c_mask,
            const float* __restrict__ wc2,
            const float* __restrict__ edge_attr,
            float* __restrict__ out) {
    __shared__ float sW[NCL];
    __shared__ int   sE64;

    const int t = threadIdx.x;

    // -------- prologue: runs concurrently with node_kernel tail (PDL) --------
    if (t < NCL) sW[t] = c_mask[t] * (wc2[t] - wc2[t + NCL]);
    if (t >= 64 && t < 96) {
        int k = t - 64;
        const long long* p = (const long long*)eidx_raw;
        long long v0 = p[k];
        long long v1 = p[k + 32];
        int ok = (v0 >= 0 && v0 < N_TOTAL && v1 >= 0 && v1 < N_TOTAL) ? 1 : 0;
        unsigned m = __ballot_sync(0xFFFFFFFFu, ok);
        if (k == 0) sE64 = (m == 0xFFFFFFFFu) ? 1 : 0;
    }
    __syncthreads();

    const float wd1  = sW[2],  wd2  = sW[5];
    const float wid  = sW[8],  wis  = sW[9],  wid2 = sW[12], wis2 = sW[13];
    const float wsd  = sW[14], wcd  = sW[15], wss  = sW[16], wcs  = sW[17];
    const float wxx  = sW[22], wxsj = sW[23], wxsi = sW[24], wsdcs = sW[25];
    const float wthd = sW[32], wsgd = sW[33], wrld = sW[34];
    const float wths = sW[35], wsgs = sW[36], wrls = sW[37];
    const int e64 = sE64;

    // gate: g_NA and out[] produced by node_kernel
#if __CUDA_ARCH__ >= 900
    cudaGridDependencySynchronize();
#endif

    int start = blockIdx.x * EDGE_CHUNK;
    int end   = min(start + EDGE_CHUNK, N_EDGES);

    for (int e0 = start + (t << 1); e0 < end; e0 += (EDGE_THREADS << 1)) {
        // start/end even -> both edges of the pair always valid
        int js[EPT], is[EPT];
        if (e64) {
            const long long* e = (const long long*)eidx_raw;
            longlong2 s0 = __ldcs(reinterpret_cast<const longlong2*>(e + e0));
            longlong2 d0 = __ldcs(reinterpret_cast<const longlong2*>(e + N_EDGES + e0));
            js[0] = (int)s0.x; js[1] = (int)s0.y;
            is[0] = (int)d0.x; is[1] = (int)d0.y;
        } else {
            const int* e = (const int*)eidx_raw;
            int2 sp = __ldcs(reinterpret_cast<const int2*>(e + e0));
            int2 dp = __ldcs(reinterpret_cast<const int2*>(e + N_EDGES + e0));
            js[0] = sp.x; js[1] = sp.y;
            is[0] = dp.x; is[1] = dp.y;
        }

        // ---- issue all gathers up front (L1-resident table + ea) ----
        float4 Nj[EPT], Ni[EPT];
        float  ea[EPT];
#pragma unroll
        for (int k = 0; k < EPT; k++) {
            Nj[k] = __ldg(&g_NA[js[k]]);
            Ni[k] = __ldg(&g_NA[is[k]]);
        }
#pragma unroll
        for (int k = 0; k < EPT; k++)
            ea[k] = __ldg(&edge_attr[(js[k] % NUM_ATOMS) * NUM_ATOMS + (is[k] % NUM_ATOMS)]);

#pragma unroll
        for (int k = 0; k < EPT; k++) {
            float xi = Ni[k].x, ai = Ni[k].y;
            float xj = Nj[k].x, bj = Nj[k].z;
            unsigned ui = __float_as_uint(Ni[k].w);
            unsigned uj = __float_as_uint(Nj[k].w);
            float2 sci = __half22float2(*reinterpret_cast<__half2*>(&ui));
            float2 scj = __half22float2(*reinterpret_cast<__half2*>(&uj));
            float si = sci.x, ci = sci.y;
            float sj = scj.x, cj = scj.y;

            float d  = xj - xi;
            float sm = xj + xi;

            // trig of d and s via angle-sum identities
            float p1 = sj * ci, p2 = cj * si, p3 = ci * cj, p4 = si * sj;
            float sind = p1 - p2, sins = p1 + p2;
            float cosd = p3 + p4, coss = p3 - p4;

            float invd = safe_inv_f(d);
            float invs = safe_inv_f(sm);

            // activations of d and s via per-edge exp (MUFU is cheap)
            float vd  = __expf(-d);
            float vs  = __expf(-sm);
            float vd2 = vd * vd, vs2 = vs * vs;
            float thd = (1.0f - vd2) * __fdividef(1.0f, 1.0f + vd2);
            float sgd = __fdividef(1.0f, 1.0f + vd);
            float ths = (1.0f - vs2) * __fdividef(1.0f, 1.0f + vs2);
            float sgs = __fdividef(1.0f, 1.0f + vs);

            float core = ai + bj;
            core = fmaf(wd1,  d,            core);
            core = fmaf(wd2,  d * d,        core);
            core = fmaf(wid,  invd,         core);
            core = fmaf(wid2, invd * invd,  core);
            core = fmaf(wis,  invs,         core);
            core = fmaf(wis2, invs * invs,  core);
            core = fmaf(wsd,  sind,         core);
            core = fmaf(wcd,  cosd,         core);
            core = fmaf(wss,  sins,         core);
            core = fmaf(wcs,  coss,         core);
            core = fmaf(wxx,  xi * xj,      core);
            core = fmaf(wxsj, xi * sj,      core);
            core = fmaf(wxsi, xj * si,      core);
            core = fmaf(wsdcs, sind * coss, core);
            core = fmaf(wthd, thd,          core);
            core = fmaf(wsgd, sgd,          core);
            core = fmaf(wrld, fmaxf(d, 0.0f),  core);
            core = fmaf(wths, ths,          core);
            core = fmaf(wsgs, sgs,          core);
            core = fmaf(wrls, fmaxf(sm, 0.0f), core);

            atomicAdd(&out[is[k]], ea[k] * core);   // segment_sum over dst
        }
    }
}

extern "C" void kernel_launch(void* const* d_in, const int* in_sizes, int n_in,
                              void* d_out, int out_size) {
    // Identify inputs by element count (robust to whether scalar `t` occupies
    // a slot). Reference order: t?, x[10000], edge_index[2000000], c_mask[38],
    // f_mask[12], wc_2[76], wf_2[24], edge_attr_all[10000].
    const float* x   = nullptr;
    const void*  ei  = nullptr;
    const float* cm  = nullptr;
    const float* fm  = nullptr;
    const float* wc2 = nullptr;
    const float* wf2 = nullptr;
    const float* ea  = nullptr;
    for (int idx = 0; idx < n_in; idx++) {
        int s = in_sizes[idx];
        if (s == 2 * N_EDGES)      ei  = d_in[idx];
        else if (s == NCL)         cm  = (const float*)d_in[idx];
        else if (s == NFL)         fm  = (const float*)d_in[idx];
        else if (s == 2 * NCL)     wc2 = (const float*)d_in[idx];
        else if (s == 2 * NFL)     wf2 = (const float*)d_in[idx];
        else if (s == N_TOTAL) {
            if (!x) x = (const float*)d_in[idx];   // x comes first
            else    ea = (const float*)d_in[idx];  // edge_attr_all second
        }
    }
    float* out = (float*)d_out;

    node_kernel<<<(N_TOTAL + 255) / 256, 256>>>(x, cm, fm, wc2, wf2, out);

    // edge_kernel with programmatic dependent launch: prologue overlaps
    // node_kernel tail; cudaGridDependencySynchronize() gates g_NA/out use.
    cudaLaunchConfig_t cfg = {};
    cfg.gridDim  = dim3(EDGE_BLOCKS, 1, 1);
    cfg.blockDim = dim3(EDGE_THREADS, 1, 1);
    cfg.dynamicSmemBytes = 0;
    cfg.stream = 0;
    cudaLaunchAttribute attr[1];
    attr[0].id = cudaLaunchAttributeProgrammaticStreamSerialization;
    attr[0].val.programmaticStreamSerializationAllowed = 1;
    cfg.attrs = attr;
    cfg.numAttrs = 1;
    cudaError_t err = cudaLaunchKernelEx(&cfg, edge_kernel, ei, cm, wc2,
                                         (const float*)ea, out);
    if (err != cudaSuccess) {
        // fallback: plain launch (still correct, just serialized)
        edge_kernel<<<EDGE_BLOCKS, EDGE_THREADS>>>(ei, cm, wc2, ea, out);
    }
}

// round 17
// speedup vs baseline: 1.1341x; 1.1341x over previous
#include <cuda_runtime.h>
#include <cuda_fp16.h>

// Problem constants (fixed by the dataset)
#define N_TOTAL   10000
#define NUM_ATOMS 100
#define N_EDGES   1000000
#define NCL 38
#define NFL 12

#define EDGE_BLOCKS  888          // 6 per SM
#define EDGE_THREADS 256
#define EPT 2
#define EDGE_CHUNK   1128         // 888 * 1128 = 1,001,664 >= 1e6; even

// Scratch (alloc-free rule: __device__ globals)
__device__ float4 g_NA[N_TOTAL];   // {x, a(i-role), b(j-role), half2(sin,cos)}

__device__ __forceinline__ float safe_inv_f(float v) {
    float w = (fabsf(v) < 0.01f) ? ((v >= 0.0f) ? 0.01f : -0.01f) : v;
    return __fdividef(1.0f, w);
}

// ---------------- node pass: F(x) -> out, plus packed per-node table ----------------
__global__ void node_kernel(const float* __restrict__ x,
                            const float* __restrict__ c_mask,
                            const float* __restrict__ f_mask,
                            const float* __restrict__ wc2,
                            const float* __restrict__ wf2,
                            float* __restrict__ out) {
    __shared__ float swc[NCL];
    __shared__ float swf[NFL];
    int t = threadIdx.x;
    if (t < NCL) swc[t] = c_mask[t] * (wc2[t] - wc2[t + NCL]);
    if (t < NFL) swf[t] = f_mask[t] * (wf2[t] - wf2[t + NFL]);
    __syncthreads();

    int n = blockIdx.x * blockDim.x + t;
    if (n >= N_TOTAL) return;
    float xv = x[n];
    float s, c;
    __sincosf(xv, &s, &c);
    float E = __expf(-xv);
    float R = __expf(xv);
    float inv  = safe_inv_f(xv);
    float inv2 = inv * inv;
    float th = (R - E) * __fdividef(1.0f, R + E);     // tanh(x)
    float sg = __fdividef(1.0f, 1.0f + E);            // sigmoid(x)
    float rl = fmaxf(xv, 0.0f);
    float x2 = xv * xv;

    float F = swf[0]
            + swf[1]*s + swf[2]*c + swf[3]*xv*s
            + swf[4]*xv + swf[5]*x2
            + swf[6]*inv + swf[7]*inv2 + swf[8]*inv2*inv
            + swf[9]*th + swf[10]*sg + swf[11]*rl;
    out[n] = F;   // F_COEF = 1; edge kernel accumulates on top

    // node-as-x_i contribution (feature idx 0,3,6,10,18,19,26,27,28)
    float a = swc[0]*xv + swc[3]*x2 + swc[6]*inv + swc[10]*inv2
            + swc[18]*s + swc[19]*c + swc[26]*th + swc[27]*sg + swc[28]*rl;
    // node-as-x_j contribution (feature idx 1,4,7,11,20,21,29,30,31)
    float b = swc[1]*xv + swc[4]*x2 + swc[7]*inv + swc[11]*inv2
            + swc[20]*s + swc[21]*c + swc[29]*th + swc[30]*sg + swc[31]*rl;

    __half2 sc = __floats2half2_rn(s, c);
    g_NA[n] = make_float4(xv, a, b, __uint_as_float(*reinterpret_cast<unsigned*>(&sc)));
}

// ---------------- edge pass: all-L1 gathers + atomics; PDL-gated ----------------
__global__ void __launch_bounds__(EDGE_THREADS, 6)
edge_kernel(const void* __restrict__ eidx_raw,
            const float* __restrict__ c_mask,
            const float* __restrict__ wc2,
            const float* __restrict__ edge_attr,
            float* __restrict__ out) {
    __shared__ float sW[NCL];
    __shared__ int   sE64;

    const int t = threadIdx.x;

    // -------- prologue: runs concurrently with node_kernel tail (PDL) --------
    if (t < NCL) sW[t] = c_mask[t] * (wc2[t] - wc2[t + NCL]);
    if (t >= 64 && t < 96) {
        int k = t - 64;
        const long long* p = (const long long*)eidx_raw;
        long long v0 = p[k];
        long long v1 = p[k + 32];
        int ok = (v0 >= 0 && v0 < N_TOTAL && v1 >= 0 && v1 < N_TOTAL) ? 1 : 0;
        unsigned m = __ballot_sync(0xFFFFFFFFu, ok);
        if (k == 0) sE64 = (m == 0xFFFFFFFFu) ? 1 : 0;
    }
    __syncthreads();

    const float wd1  = sW[2],  wd2  = sW[5];
    const float wid  = sW[8],  wis  = sW[9],  wid2 = sW[12], wis2 = sW[13];
    const float wsd  = sW[14], wcd  = sW[15], wss  = sW[16], wcs  = sW[17];
    const float wxx  = sW[22], wxsj = sW[23], wxsi = sW[24], wsdcs = sW[25];
    const float wthd = sW[32], wsgd = sW[33], wrld = sW[34];
    const float wths = sW[35], wsgs = sW[36], wrls = sW[37];
    const int e64 = sE64;

    // gate: g_NA and out[] produced by node_kernel
#if __CUDA_ARCH__ >= 900
    cudaGridDependencySynchronize();
#endif

    int start = blockIdx.x * EDGE_CHUNK;
    int end   = min(start + EDGE_CHUNK, N_EDGES);

    for (int e0 = start + (t << 1); e0 < end; e0 += (EDGE_THREADS << 1)) {
        // start/end even -> both edges of the pair always valid
        int js[EPT], is[EPT];
        if (e64) {
            const long long* e = (const long long*)eidx_raw;
            longlong2 s0 = __ldcs(reinterpret_cast<const longlong2*>(e + e0));
            longlong2 d0 = __ldcs(reinterpret_cast<const longlong2*>(e + N_EDGES + e0));
            js[0] = (int)s0.x; js[1] = (int)s0.y;
            is[0] = (int)d0.x; is[1] = (int)d0.y;
        } else {
            const int* e = (const int*)eidx_raw;
            int2 sp = __ldcs(reinterpret_cast<const int2*>(e + e0));
            int2 dp = __ldcs(reinterpret_cast<const int2*>(e + N_EDGES + e0));
            js[0] = sp.x; js[1] = sp.y;
            is[0] = dp.x; is[1] = dp.y;
        }

        // ---- issue all gathers up front (L1-resident table + ea) ----
        float4 Nj[EPT], Ni[EPT];
        float  ea[EPT];
#pragma unroll
        for (int k = 0; k < EPT; k++) {
            Nj[k] = __ldg(&g_NA[js[k]]);
            Ni[k] = __ldg(&g_NA[is[k]]);
        }
#pragma unroll
        for (int k = 0; k < EPT; k++)
            ea[k] = __ldg(&edge_attr[(js[k] % NUM_ATOMS) * NUM_ATOMS + (is[k] % NUM_ATOMS)]);

#pragma unroll
        for (int k = 0; k < EPT; k++) {
            float xi = Ni[k].x, ai = Ni[k].y;
            float xj = Nj[k].x, bj = Nj[k].z;
            unsigned ui = __float_as_uint(Ni[k].w);
            unsigned uj = __float_as_uint(Nj[k].w);
            float2 sci = __half22float2(*reinterpret_cast<__half2*>(&ui));
            float2 scj = __half22float2(*reinterpret_cast<__half2*>(&uj));
            float si = sci.x, ci = sci.y;
            float sj = scj.x, cj = scj.y;

            float d  = xj - xi;
            float sm = xj + xi;

            // trig of d and s via angle-sum identities
            float p1 = sj * ci, p2 = cj * si, p3 = ci * cj, p4 = si * sj;
            float sind = p1 - p2, sins = p1 + p2;
            float cosd = p3 + p4, coss = p3 - p4;

            float invd = safe_inv_f(d);
            float invs = safe_inv_f(sm);

            // activations of d and s via per-edge exp (MUFU is cheap)
            float vd  = __expf(-d);
            float vs  = __expf(-sm);
            float vd2 = vd * vd, vs2 = vs * vs;
            float thd = (1.0f - vd2) * __fdividef(1.0f, 1.0f + vd2);
            float sgd = __fdividef(1.0f, 1.0f + vd);
            float ths = (1.0f - vs2) * __fdividef(1.0f, 1.0f + vs2);
            float sgs = __fdividef(1.0f, 1.0f + vs);

            float core = ai + bj;
            core = fmaf(wd1,  d,            core);
            core = fmaf(wd2,  d * d,        core);
            core = fmaf(wid,  invd,         core);
            core = fmaf(wid2, invd * invd,  core);
            core = fmaf(wis,  invs,         core);
            core = fmaf(wis2, invs * invs,  core);
            core = fmaf(wsd,  sind,         core);
            core = fmaf(wcd,  cosd,         core);
            core = fmaf(wss,  sins,         core);
            core = fmaf(wcs,  coss,         core);
            core = fmaf(wxx,  xi * xj,      core);
            core = fmaf(wxsj, xi * sj,      core);
            core = fmaf(wxsi, xj * si,      core);
            core = fmaf(wsdcs, sind * coss, core);
            core = fmaf(wthd, thd,          core);
            core = fmaf(wsgd, sgd,          core);
            core = fmaf(wrld, fmaxf(d, 0.0f),  core);
            core = fmaf(wths, ths,          core);
            core = fmaf(wsgs, sgs,          core);
            core = fmaf(wrls, fmaxf(sm, 0.0f), core);

            atomicAdd(&out[is[k]], ea[k] * core);   // segment_sum over dst
        }
    }
}

extern "C" void kernel_launch(void* const* d_in, const int* in_sizes, int n_in,
                              void* d_out, int out_size) {
    // Identify inputs by element count (robust to whether scalar `t` occupies
    // a slot). Reference order: t?, x[10000], edge_index[2000000], c_mask[38],
    // f_mask[12], wc_2[76], wf_2[24], edge_attr_all[10000].
    const float* x   = nullptr;
    const void*  ei  = nullptr;
    const float* cm  = nullptr;
    const float* fm  = nullptr;
    const float* wc2 = nullptr;
    const float* wf2 = nullptr;
    const float* ea  = nullptr;
    for (int idx = 0; idx < n_in; idx++) {
        int s = in_sizes[idx];
        if (s == 2 * N_EDGES)      ei  = d_in[idx];
        else if (s == NCL)         cm  = (const float*)d_in[idx];
        else if (s == NFL)         fm  = (const float*)d_in[idx];
        else if (s == 2 * NCL)     wc2 = (const float*)d_in[idx];
        else if (s == 2 * NFL)     wf2 = (const float*)d_in[idx];
        else if (s == N_TOTAL) {
            if (!x) x = (const float*)d_in[idx];   // x comes first
            else    ea = (const float*)d_in[idx];  // edge_attr_all second
        }
    }
    float* out = (float*)d_out;

    node_kernel<<<(N_TOTAL + 255) / 256, 256>>>(x, cm, fm, wc2, wf2, out);

    // edge_kernel with programmatic dependent launch: prologue overlaps
    // node_kernel tail; cudaGridDependencySynchronize() gates g_NA/out use.
    cudaLaunchConfig_t cfg = {};
    cfg.gridDim  = dim3(EDGE_BLOCKS, 1, 1);
    cfg.blockDim = dim3(EDGE_THREADS, 1, 1);
    cfg.dynamicSmemBytes = 0;
    cfg.stream = 0;
    cudaLaunchAttribute attr[1];
    attr[0].id = cudaLaunchAttributeProgrammaticStreamSerialization;
    attr[0].val.programmaticStreamSerializationAllowed = 1;
    cfg.attrs = attr;
    cfg.numAttrs = 1;
    cudaError_t err = cudaLaunchKernelEx(&cfg, edge_kernel, ei, cm, wc2,
                                         (const float*)ea, out);
    if (err != cudaSuccess) {
        // fallback: plain launch (still correct, just serialized)
        edge_kernel<<<EDGE_BLOCKS, EDGE_THREADS>>>(ei, cm, wc2, ea, out);
    }
}